// round 1
// baseline (speedup 1.0000x reference)
#include <cuda_runtime.h>

#define NATOMS 2048
#define CATOM  128
#define CPAIR  16
#define NHEADS 4

// ---------------- scratch (no allocations allowed) ----------------
__device__ float g_qn  [NATOMS*CATOM];
__device__ float g_q   [NATOMS*CATOM];
__device__ float g_k   [NATOMS*CATOM];
__device__ float g_v   [NATOMS*CATOM];
__device__ float g_gate[NATOMS*CATOM];
__device__ float g_go  [NATOMS*CATOM];
__device__ float g_ql1 [NATOMS*CATOM];
__device__ float g_h   [NATOMS*4*CATOM];

// ---------------- LayerNorm over C=128 (one block per row) ----------------
__global__ __launch_bounds__(128) void ln_kernel(
    const float* __restrict__ x, const float* __restrict__ w,
    const float* __restrict__ b, float* __restrict__ y)
{
    int row = blockIdx.x;
    int t = threadIdx.x;
    float v = x[(size_t)row*CATOM + t];
    float s = v, s2 = v*v;
    #pragma unroll
    for (int o = 16; o > 0; o >>= 1) {
        s  += __shfl_xor_sync(0xffffffffu, s,  o);
        s2 += __shfl_xor_sync(0xffffffffu, s2, o);
    }
    __shared__ float ps[4], ps2[4];
    int warp = t >> 5;
    if ((t & 31) == 0) { ps[warp] = s; ps2[warp] = s2; }
    __syncthreads();
    float sum  = ps[0]  + ps[1]  + ps[2]  + ps[3];
    float sum2 = ps2[0] + ps2[1] + ps2[2] + ps2[3];
    float mu   = sum  * (1.f/CATOM);
    float var  = sum2 * (1.f/CATOM) - mu*mu;
    float rstd = rsqrtf(var + 1e-5f);
    y[(size_t)row*CATOM + t] = (v - mu) * rstd * w[t] + b[t];
}

// ---------------- generic fp32 GEMM: C[M,N] = A[M,K] @ B[N,K]^T ----------------
// op: 0 = none, 1 = sigmoid, 2 = relu.  bias (len N) and resid (shape of C) optional.
__device__ __forceinline__ void gemm_body(
    const float* __restrict__ A, const float* __restrict__ B,
    const float* __restrict__ bias, const float* __restrict__ resid,
    float* __restrict__ C, int N, int K, int op)
{
    __shared__ float As[16][68];
    __shared__ float Bs[16][68];
    const int tid = threadIdx.x;
    const int tx = tid & 15, ty = tid >> 4;
    const int m0 = blockIdx.y * 64, n0 = blockIdx.x * 64;

    float acc[4][4];
    #pragma unroll
    for (int i = 0; i < 4; i++)
        #pragma unroll
        for (int j = 0; j < 4; j++) acc[i][j] = 0.f;

    const int row = tid >> 2;
    const int c4  = (tid & 3) * 4;

    for (int k0 = 0; k0 < K; k0 += 16) {
        float4 a  = *(const float4*)&A[(size_t)(m0+row)*K + k0 + c4];
        float4 bb = *(const float4*)&B[(size_t)(n0+row)*K + k0 + c4];
        As[c4+0][row] = a.x;  As[c4+1][row] = a.y;  As[c4+2][row] = a.z;  As[c4+3][row] = a.w;
        Bs[c4+0][row] = bb.x; Bs[c4+1][row] = bb.y; Bs[c4+2][row] = bb.z; Bs[c4+3][row] = bb.w;
        __syncthreads();
        #pragma unroll
        for (int kk = 0; kk < 16; kk++) {
            float av[4], bv[4];
            #pragma unroll
            for (int i = 0; i < 4; i++) { av[i] = As[kk][ty + 16*i]; bv[i] = Bs[kk][tx + 16*i]; }
            #pragma unroll
            for (int i = 0; i < 4; i++)
                #pragma unroll
                for (int j = 0; j < 4; j++)
                    acc[i][j] = fmaf(av[i], bv[j], acc[i][j]);
        }
        __syncthreads();
    }

    #pragma unroll
    for (int i = 0; i < 4; i++) {
        int mm = m0 + ty + 16*i;
        #pragma unroll
        for (int j = 0; j < 4; j++) {
            int nn = n0 + tx + 16*j;
            float v = acc[i][j];
            if (bias)    v += bias[nn];
            if (op == 1) v = 1.f / (1.f + __expf(-v));
            else if (op == 2) v = fmaxf(v, 0.f);
            if (resid)   v += resid[(size_t)mm*N + nn];
            C[(size_t)mm*N + nn] = v;
        }
    }
}

__global__ __launch_bounds__(256) void gemm_nt(
    const float* __restrict__ A, const float* __restrict__ B,
    const float* __restrict__ bias, const float* __restrict__ resid,
    float* __restrict__ C, int N, int K, int op)
{
    gemm_body(A, B, bias, resid, C, N, K, op);
}

// fused Q/K/V/Gate projection (blockIdx.z picks weight & output)
__global__ __launch_bounds__(256) void gemm_qkvg(
    const float* __restrict__ Wq, const float* __restrict__ bq,
    const float* __restrict__ Wk, const float* __restrict__ Wv,
    const float* __restrict__ Wg)
{
    int z = blockIdx.z;
    const float* B = (z==0) ? Wq : (z==1) ? Wk : (z==2) ? Wv : Wg;
    float*       O = (z==0) ? g_q : (z==1) ? g_k : (z==2) ? g_v : g_gate;
    const float* bias = (z==0) ? bq : nullptr;
    int op = (z==3) ? 1 : 0;   // sigmoid for gate
    gemm_body(g_qn, B, bias, nullptr, O, CATOM, CATOM, op);
}

// ---------------- fused pair-biased flash attention ----------------
// Grid: 128 CTAs, each handles 16 query rows, all 4 heads.
// pair group = (row, head): 4 lanes, each lane owns jj = lane + 4u (u=0..7) of
// each 32-wide key tile, keeps its own online-softmax state + partial acc[32],
// combined across the 4 lanes at the end.

__device__ __forceinline__ int kswz(int f4col) {
    // keep 16B-group (head) bits, rotate low-3 by 2*head to spread bank groups
    return (f4col & 24) | (((f4col & 7) + 2*(f4col >> 3)) & 7);
}

__global__ __launch_bounds__(256) void attn_kernel(
    const float* __restrict__ plm,  const float* __restrict__ beta,
    const float* __restrict__ npw,  const float* __restrict__ npb,
    const float* __restrict__ Wpb)
{
    __shared__ float k_s[32*132];
    __shared__ float v_s[32*132];
    __shared__ float bias_s[64*33];
    __shared__ float ww[64];
    __shared__ float wcs[4];

    const int tid = threadIdx.x;
    const int i0  = blockIdx.x * 16;

    if (tid < 64) ww[tid] = npw[tid & 15] * Wpb[tid];   // (w * Wpb[h][c])
    if (tid < 4) {
        float s = 0.f;
        #pragma unroll
        for (int c = 0; c < 16; c++) s += npb[c] * Wpb[tid*16 + c];
        wcs[tid] = s;                                   // (b . Wpb[h])
    }

    const int pair = tid >> 2;
    const int r    = pair >> 2;      // 0..15
    const int h    = pair & 3;       // 0..3
    const int lane = tid & 3;        // 0..3

    // q[r, h, :] pre-scaled by 1/sqrt(32), in registers
    float4 q4[8];
    {
        const float* qp = g_q + (size_t)(i0 + r)*CATOM + h*32;
        const float qs = 0.17677669529663687f;
        #pragma unroll
        for (int c4 = 0; c4 < 8; c4++) {
            float4 t = *(const float4*)&qp[c4*4];
            t.x *= qs; t.y *= qs; t.z *= qs; t.w *= qs;
            q4[c4] = t;
        }
    }

    float m = -1e30f, lsum = 0.f;
    float acc[32];
    #pragma unroll
    for (int c = 0; c < 32; c++) acc[c] = 0.f;

    for (int jt = 0; jt < NATOMS/32; jt++) {
        const int j0 = jt * 32;
        __syncthreads();   // previous tile fully consumed (also covers ww/wcs init)

        // --- stage K/V tile (swizzled) ---
        {
            const int f4 = tid & 31;
            const int rb = tid >> 5;
            const int sw = kswz(f4) * 4;
            #pragma unroll
            for (int p = 0; p < 4; p++) {
                int row = rb + p*8;
                *(float4*)&k_s[row*132 + sw] = *(const float4*)&g_k[(size_t)(j0+row)*CATOM + f4*4];
                *(float4*)&v_s[row*132 + sw] = *(const float4*)&g_v[(size_t)(j0+row)*CATOM + f4*4];
            }
        }

        // --- pair bias: LN16(plm) . (w*Wpb_h) * rstd + b.Wpb_h + beta ---
        #pragma unroll
        for (int rep = 0; rep < 2; rep++) {
            const int idx = tid + rep*256;
            const int rr = idx >> 5, jj = idx & 31;
            const float* pp = plm + ((size_t)(i0+rr)*NATOMS + (j0+jj))*CPAIR;
            float x[16];
            #pragma unroll
            for (int t4 = 0; t4 < 4; t4++) {
                float4 tv = *(const float4*)&pp[t4*4];
                x[t4*4+0] = tv.x; x[t4*4+1] = tv.y; x[t4*4+2] = tv.z; x[t4*4+3] = tv.w;
            }
            float sum = 0.f, sum2 = 0.f;
            #pragma unroll
            for (int c = 0; c < 16; c++) { sum += x[c]; sum2 = fmaf(x[c], x[c], sum2); }
            float mu   = sum * 0.0625f;
            float var  = fmaf(-mu, mu, sum2 * 0.0625f);
            float rstd = rsqrtf(var + 1e-5f);
            float bm   = beta[(size_t)(i0+rr)*NATOMS + (j0+jj)];
            #pragma unroll
            for (int hh = 0; hh < 4; hh++) {
                float d = 0.f;
                #pragma unroll
                for (int c = 0; c < 16; c++) d = fmaf(x[c] - mu, ww[hh*16 + c], d);
                bias_s[(rr*4 + hh)*33 + jj] = fmaf(rstd, d, wcs[hh] + bm);
            }
        }
        __syncthreads();

        // --- scores for this lane's 8 keys ---
        float s[8];
        #pragma unroll
        for (int u = 0; u < 8; u++) {
            const int jj = lane + u*4;
            const float* kr = &k_s[jj*132];
            float a = 0.f;
            #pragma unroll
            for (int c4 = 0; c4 < 8; c4++) {
                float4 k4 = *(const float4*)&kr[kswz(h*8 + c4)*4];
                a = fmaf(q4[c4].x, k4.x, fmaf(q4[c4].y, k4.y,
                    fmaf(q4[c4].z, k4.z, fmaf(q4[c4].w, k4.w, a))));
            }
            s[u] = a + bias_s[(r*4 + h)*33 + jj];
        }

        // --- per-lane online softmax + AV ---
        float tmax = s[0];
        #pragma unroll
        for (int u = 1; u < 8; u++) tmax = fmaxf(tmax, s[u]);
        float mnew = fmaxf(m, tmax);
        float corr = __expf(m - mnew);
        lsum *= corr;
        #pragma unroll
        for (int c = 0; c < 32; c++) acc[c] *= corr;
        #pragma unroll
        for (int u = 0; u < 8; u++) {
            const int jj = lane + u*4;
            float p = __expf(s[u] - mnew);
            lsum += p;
            const float* vr = &v_s[jj*132];
            #pragma unroll
            for (int c4 = 0; c4 < 8; c4++) {
                float4 v4 = *(const float4*)&vr[kswz(h*8 + c4)*4];
                acc[c4*4+0] = fmaf(p, v4.x, acc[c4*4+0]);
                acc[c4*4+1] = fmaf(p, v4.y, acc[c4*4+1]);
                acc[c4*4+2] = fmaf(p, v4.z, acc[c4*4+2]);
                acc[c4*4+3] = fmaf(p, v4.w, acc[c4*4+3]);
            }
        }
        m = mnew;
    }

    // --- combine the 4 lanes of this (row, head) ---
    float mm1  = fmaxf(m, __shfl_xor_sync(0xffffffffu, m, 1));
    float mmax = fmaxf(mm1, __shfl_xor_sync(0xffffffffu, mm1, 2));
    float fac  = __expf(m - mmax);
    float l = lsum * fac;
    l += __shfl_xor_sync(0xffffffffu, l, 1);
    l += __shfl_xor_sync(0xffffffffu, l, 2);
    #pragma unroll
    for (int c = 0; c < 32; c++) {
        float a = acc[c] * fac;
        a += __shfl_xor_sync(0xffffffffu, a, 1);
        a += __shfl_xor_sync(0xffffffffu, a, 2);
        acc[c] = a;
    }
    if (lane == 0) {
        float inv = 1.f / l;
        const float* gp = &g_gate[(size_t)(i0 + r)*CATOM + h*32];
        float*       op = &g_go  [(size_t)(i0 + r)*CATOM + h*32];
        #pragma unroll
        for (int c4 = 0; c4 < 8; c4++) {
            float4 g4 = *(const float4*)&gp[c4*4];
            float4 o;
            o.x = acc[c4*4+0]*inv*g4.x;
            o.y = acc[c4*4+1]*inv*g4.y;
            o.z = acc[c4*4+2]*inv*g4.z;
            o.w = acc[c4*4+3]*inv*g4.w;
            *(float4*)&op[c4*4] = o;
        }
    }
}

// ---------------- host launch ----------------
extern "C" void kernel_launch(void* const* d_in, const int* in_sizes, int n_in,
                              void* d_out, int out_size)
{
    const float* ql  = (const float*)d_in[0];
    // d_in[1] = cl (unused by reference)
    const float* plm = (const float*)d_in[2];
    const float* beta= (const float*)d_in[3];
    const float* nqw = (const float*)d_in[4];
    const float* nqb = (const float*)d_in[5];
    const float* npw = (const float*)d_in[6];
    const float* npb = (const float*)d_in[7];
    const float* Wq  = (const float*)d_in[8];
    const float* bq  = (const float*)d_in[9];
    const float* Wk  = (const float*)d_in[10];
    const float* Wv  = (const float*)d_in[11];
    const float* Wpb = (const float*)d_in[12];
    const float* Wg  = (const float*)d_in[13];
    const float* Wo  = (const float*)d_in[14];
    const float* tlw = (const float*)d_in[15];
    const float* tlb = (const float*)d_in[16];
    const float* W1  = (const float*)d_in[17];
    const float* b1  = (const float*)d_in[18];
    const float* W2  = (const float*)d_in[19];
    const float* b2  = (const float*)d_in[20];

    float *qn, *go, *ql1, *hh;
    cudaGetSymbolAddress((void**)&qn,  g_qn);
    cudaGetSymbolAddress((void**)&go,  g_go);
    cudaGetSymbolAddress((void**)&ql1, g_ql1);
    cudaGetSymbolAddress((void**)&hh,  g_h);

    // 1. ql_norm
    ln_kernel<<<NATOMS, 128>>>(ql, nqw, nqb, qn);
    // 2. q, k, v, gate
    gemm_qkvg<<<dim3(2, 32, 4), 256>>>(Wq, bq, Wk, Wv, Wg);
    // 3. pair-biased attention -> go = gate * attn_out
    attn_kernel<<<NATOMS/16, 256>>>(plm, beta, npw, npb, Wpb);
    // 4. ql1 = ql + go @ Wo^T
    gemm_nt<<<dim3(2, 32), 256>>>(go, Wo, nullptr, ql, ql1, CATOM, CATOM, 0);
    // 5. t = LN(ql1)
    ln_kernel<<<NATOMS, 128>>>(ql1, tlw, tlb, qn);
    // 6. h = relu(t @ W1^T + b1)
    gemm_nt<<<dim3(8, 32), 256>>>(qn, W1, b1, nullptr, hh, 4*CATOM, CATOM, 2);
    // 7. out = ql1 + h @ W2^T + b2
    gemm_nt<<<dim3(2, 32), 256>>>(hh, W2, b2, ql1, (float*)d_out, CATOM, 4*CATOM, 0);
}